// round 12
// baseline (speedup 1.0000x reference)
#include <cuda_runtime.h>
#include <cuda_bf16.h>
#include <math.h>
#include <stdint.h>

// ---------------------------------------------------------------------------
// StackMSA round 12: tail packing — add_pe(scale1) fused into pool+LN,
// scatter fused into the last small-GEMM epilogue. GEMM/attention frozen
// (HMMA pipe floor reached, verified R5/R9/R11).
// ---------------------------------------------------------------------------

#define NTOK0 65536
#define NTOK1 4096
#define NTOKA 69632
#define MB1T 512
#define ATTN_SMEM 61440
#define GEMM_SMEM 98304     // 3 stages x (16KB A + 16KB B)

__device__ float g_X[69632 * 256];
__device__ float g_PE[2 * 256 * 256];
__device__ float g_G[4096 * 256];
__device__ __nv_bfloat16 g_Hb[69632 * 256];
__device__ __nv_bfloat16 g_QKVb[69632 * 768];
__device__ __nv_bfloat16 g_Tb[69632 * 1024];
__device__ __nv_bfloat16 g_WT[1572864];

__device__ __forceinline__ float gelu_exact(float x) {
    return 0.5f * x * (1.0f + erff(x * 0.70710678118654752f));
}

__device__ __forceinline__ uint32_t smem_u32(const void* p) {
    uint32_t a;
    asm("{ .reg .u64 t; cvta.to.shared.u64 t, %1; cvt.u32.u64 %0, t; }"
        : "=r"(a) : "l"(p));
    return a;
}

#define SWZ128(o) ((o) ^ (((o) >> 3) & 0x70))
#define CP16(dst, src) \
    asm volatile("cp.async.cg.shared.global [%0], [%1], 16;" :: "r"(dst), "l"(src))
#define CPCOMMIT() asm volatile("cp.async.commit_group;" ::: "memory")
#define CPWAIT1() asm volatile("cp.async.wait_group 1;" ::: "memory")

#define LDSM_X4(r, addr) \
    asm volatile("ldmatrix.sync.aligned.m8n8.x4.shared.b16 {%0,%1,%2,%3}, [%4];" \
                 : "=r"((r)[0]), "=r"((r)[1]), "=r"((r)[2]), "=r"((r)[3]) : "r"(addr))
#define LDSM_X4T(r, addr) \
    asm volatile("ldmatrix.sync.aligned.m8n8.x4.trans.shared.b16 {%0,%1,%2,%3}, [%4];" \
                 : "=r"((r)[0]), "=r"((r)[1]), "=r"((r)[2]), "=r"((r)[3]) : "r"(addr))
#define MMA16816(d, a, b0, b1) \
    asm volatile("mma.sync.aligned.m16n8k16.row.col.f32.bf16.bf16.f32 " \
                 "{%0,%1,%2,%3}, {%4,%5,%6,%7}, {%8,%9}, {%0,%1,%2,%3};" \
                 : "+f"((d)[0]), "+f"((d)[1]), "+f"((d)[2]), "+f"((d)[3]) \
                 : "r"((a)[0]), "r"((a)[1]), "r"((a)[2]), "r"((a)[3]), \
                   "r"(b0), "r"(b1))

__device__ __forceinline__ uint32_t bf2u(float x, float y) {
    __nv_bfloat162 h = __float22bfloat162_rn(make_float2(x, y));
    return *(uint32_t*)&h;
}

// scatter row map: f -> gwin*256+tt
__device__ __forceinline__ int scat_row(int f) {
    int b = f >> 10, h = (f >> 7) & 7, w = (f >> 4) & 7;
    int r1 = (f >> 2) & 3, r2 = f & 3;
    int gr = h * 4 + r1, gc = w * 4 + r2;
    int gwin = b * 4 + (gr >> 4) * 2 + (gc >> 4);
    int tt = (gr & 15) * 16 + (gc & 15);
    return gwin * 256 + tt;
}

// ---------------------------------------------------------------------------
__global__ void smsa_posemb_kernel(const float* __restrict__ w1,
                                   const float* __restrict__ b1,
                                   const float* __restrict__ w2,
                                   float* __restrict__ pe) {
    int t = blockIdx.x, s = blockIdx.y, tid = threadIdx.x;
    __shared__ float hid[512];
    float c0 = (float)((t >> 4) - 8) * 0.125f;
    float c1 = (float)((t & 15) - 8) * 0.125f;
    const float* W1 = w1 + s * 1024;
    const float* B1 = b1 + s * 512;
    for (int k = tid; k < 512; k += 256)
        hid[k] = fmaxf(fmaf(c0, W1[k], fmaf(c1, W1[512 + k], B1[k])), 0.0f);
    __syncthreads();
    const float* W2 = w2 + s * 512 * 256;
    float acc = 0.0f;
#pragma unroll 8
    for (int k = 0; k < 512; k++) acc = fmaf(hid[k], W2[k * 256 + tid], acc);
    pe[s * 65536 + t * 256 + tid] = acc;
}

__global__ __launch_bounds__(256) void smsa_add_pe_ln_kernel(
    const float* __restrict__ x, const float* __restrict__ pe,
    float* __restrict__ y, __nv_bfloat16* __restrict__ hb,
    const float* __restrict__ gg, const float* __restrict__ bb) {
    int tok = blockIdx.x * 8 + (threadIdx.x >> 5);
    int lane = threadIdx.x & 31;
    const float4* xr = (const float4*)(x + (size_t)tok * 256);
    const float4* pr = (const float4*)(pe + (size_t)(tok & 255) * 256);
    float4 v0 = xr[lane], v1 = xr[lane + 32];
    float4 p0 = pr[lane], p1 = pr[lane + 32];
    v0.x += p0.x; v0.y += p0.y; v0.z += p0.z; v0.w += p0.w;
    v1.x += p1.x; v1.y += p1.y; v1.z += p1.z; v1.w += p1.w;
    float4* yr = (float4*)(y + (size_t)tok * 256);
    yr[lane] = v0;
    yr[lane + 32] = v1;
    float s = v0.x + v0.y + v0.z + v0.w + v1.x + v1.y + v1.z + v1.w;
    float ss = v0.x * v0.x + v0.y * v0.y + v0.z * v0.z + v0.w * v0.w +
               v1.x * v1.x + v1.y * v1.y + v1.z * v1.z + v1.w * v1.w;
#pragma unroll
    for (int o = 16; o > 0; o >>= 1) {
        s += __shfl_xor_sync(0xffffffffu, s, o);
        ss += __shfl_xor_sync(0xffffffffu, ss, o);
    }
    float mean = s * 0.00390625f;
    float var = ss * 0.00390625f - mean * mean;
    float rstd = rsqrtf(var + 1e-5f);
    float4 g0 = ((const float4*)gg)[lane], g1 = ((const float4*)gg)[lane + 32];
    float4 b0 = ((const float4*)bb)[lane], b1 = ((const float4*)bb)[lane + 32];
    uint2 o0, o1;
    o0.x = bf2u((v0.x - mean) * rstd * g0.x + b0.x, (v0.y - mean) * rstd * g0.y + b0.y);
    o0.y = bf2u((v0.z - mean) * rstd * g0.z + b0.z, (v0.w - mean) * rstd * g0.w + b0.w);
    o1.x = bf2u((v1.x - mean) * rstd * g1.x + b1.x, (v1.y - mean) * rstd * g1.y + b1.y);
    o1.y = bf2u((v1.z - mean) * rstd * g1.z + b1.z, (v1.w - mean) * rstd * g1.w + b1.w);
    uint2* hr = (uint2*)(hb + (size_t)tok * 256);
    hr[lane] = o0;
    hr[lane + 32] = o1;
}

// fused add_pe(scale1) + pool + LN1(scale1): v = scale1 + pe + max
__global__ __launch_bounds__(256) void smsa_pool_ln_kernel(
    const float* __restrict__ x0, const float* __restrict__ scale1,
    const float* __restrict__ pe1, float* __restrict__ x1,
    __nv_bfloat16* __restrict__ hb1,
    const float* __restrict__ gg, const float* __restrict__ bb) {
    __shared__ float red[16];
    int gid = blockIdx.x, c = threadIdx.x;
    int b = gid >> 10, gr = (gid >> 5) & 31, gc = gid & 31;
    int h = gr >> 2, r1 = gr & 3, w = gc >> 2, r2 = gc & 3;
    int fw = (b * 8 + h) * 8 + w;
    const float* base = x0 + ((size_t)fw * 256 + r1 * 64 + r2 * 4) * 256 + c;
    float m = -1e30f;
#pragma unroll
    for (int p1 = 0; p1 < 4; p1++)
#pragma unroll
        for (int p2 = 0; p2 < 4; p2++)
            m = fmaxf(m, base[(p1 * 16 + p2) * 256]);
    int gwin = b * 4 + (gr >> 4) * 2 + (gc >> 4);
    int tt = (gr & 15) * 16 + (gc & 15);
    size_t idx = ((size_t)gwin * 256 + tt) * 256 + c;
    float v = (scale1[idx] + pe1[(size_t)tt * 256 + c]) + m;
    x1[idx] = v;
    float s = v, q = v * v;
#pragma unroll
    for (int o = 16; o > 0; o >>= 1) {
        s += __shfl_xor_sync(0xffffffffu, s, o);
        q += __shfl_xor_sync(0xffffffffu, q, o);
    }
    int warp = c >> 5, lane = c & 31;
    if (lane == 0) { red[warp] = s; red[warp + 8] = q; }
    __syncthreads();
    float S = 0.0f, Q = 0.0f;
#pragma unroll
    for (int wi = 0; wi < 8; wi++) { S += red[wi]; Q += red[wi + 8]; }
    float mean = S * 0.00390625f;
    float var = Q * 0.00390625f - mean * mean;
    float rstd = rsqrtf(var + 1e-5f);
    hb1[idx] = __float2bfloat16((v - mean) * rstd * gg[c] + bb[c]);
}

// LayerNorm, segmented params
__global__ __launch_bounds__(256) void smsa_ln_kernel(
    const float* __restrict__ x, __nv_bfloat16* __restrict__ y,
    const float* __restrict__ gg0, const float* __restrict__ bb0,
    const float* __restrict__ gg1, const float* __restrict__ bb1, int bnd) {
    int tok = blockIdx.x * 8 + (threadIdx.x >> 5);
    int lane = threadIdx.x & 31;
    const float* gg = tok < bnd ? gg0 : gg1;
    const float* bb = tok < bnd ? bb0 : bb1;
    const float4* row = (const float4*)(x + (size_t)tok * 256);
    float4 v0 = row[lane], v1 = row[lane + 32];
    float s = v0.x + v0.y + v0.z + v0.w + v1.x + v1.y + v1.z + v1.w;
    float ss = v0.x * v0.x + v0.y * v0.y + v0.z * v0.z + v0.w * v0.w +
               v1.x * v1.x + v1.y * v1.y + v1.z * v1.z + v1.w * v1.w;
#pragma unroll
    for (int o = 16; o > 0; o >>= 1) {
        s += __shfl_xor_sync(0xffffffffu, s, o);
        ss += __shfl_xor_sync(0xffffffffu, ss, o);
    }
    float mean = s * 0.00390625f;
    float var = ss * 0.00390625f - mean * mean;
    float rstd = rsqrtf(var + 1e-5f);
    float4 g0 = ((const float4*)gg)[lane], g1 = ((const float4*)gg)[lane + 32];
    float4 b0 = ((const float4*)bb)[lane], b1 = ((const float4*)bb)[lane + 32];
    uint2 o0, o1;
    o0.x = bf2u((v0.x - mean) * rstd * g0.x + b0.x, (v0.y - mean) * rstd * g0.y + b0.y);
    o0.y = bf2u((v0.z - mean) * rstd * g0.z + b0.z, (v0.w - mean) * rstd * g0.w + b0.w);
    o1.x = bf2u((v1.x - mean) * rstd * g1.x + b1.x, (v1.y - mean) * rstd * g1.y + b1.y);
    o1.y = bf2u((v1.z - mean) * rstd * g1.z + b1.z, (v1.w - mean) * rstd * g1.w + b1.w);
    uint2* yr = (uint2*)(y + (size_t)tok * 256);
    yr[lane] = o0;
    yr[lane + 32] = o1;
}

// fused gather + LN
__global__ __launch_bounds__(256) void smsa_gather_ln_kernel(
    const float* __restrict__ x1, float* __restrict__ g,
    __nv_bfloat16* __restrict__ hbo,
    const float* __restrict__ gg, const float* __restrict__ bb) {
    int f = blockIdx.x * 8 + (threadIdx.x >> 5);
    int lane = threadIdx.x & 31;
    int row_in = scat_row(f);
    const float4* row = (const float4*)(x1 + (size_t)row_in * 256);
    float4 v0 = row[lane], v1 = row[lane + 32];
    float4* grow = (float4*)(g + (size_t)f * 256);
    grow[lane] = v0;
    grow[lane + 32] = v1;
    float s = v0.x + v0.y + v0.z + v0.w + v1.x + v1.y + v1.z + v1.w;
    float ss = v0.x * v0.x + v0.y * v0.y + v0.z * v0.z + v0.w * v0.w +
               v1.x * v1.x + v1.y * v1.y + v1.z * v1.z + v1.w * v1.w;
#pragma unroll
    for (int o = 16; o > 0; o >>= 1) {
        s += __shfl_xor_sync(0xffffffffu, s, o);
        ss += __shfl_xor_sync(0xffffffffu, ss, o);
    }
    float mean = s * 0.00390625f;
    float var = ss * 0.00390625f - mean * mean;
    float rstd = rsqrtf(var + 1e-5f);
    float4 g0 = ((const float4*)gg)[lane], g1 = ((const float4*)gg)[lane + 32];
    float4 b0 = ((const float4*)bb)[lane], b1 = ((const float4*)bb)[lane + 32];
    uint2 o0, o1;
    o0.x = bf2u((v0.x - mean) * rstd * g0.x + b0.x, (v0.y - mean) * rstd * g0.y + b0.y);
    o0.y = bf2u((v0.z - mean) * rstd * g0.z + b0.z, (v0.w - mean) * rstd * g0.w + b0.w);
    o1.x = bf2u((v1.x - mean) * rstd * g1.x + b1.x, (v1.y - mean) * rstd * g1.y + b1.y);
    o1.y = bf2u((v1.z - mean) * rstd * g1.z + b1.z, (v1.w - mean) * rstd * g1.w + b1.w);
    uint2* hr = (uint2*)(hbo + (size_t)f * 256);
    hr[lane] = o0;
    hr[lane + 32] = o1;
}

// ---------------------------------------------------------------------------
struct TrJobs {
    const float* W[8];
    __nv_bfloat16* Wt[8];
    int K[8], N[8], blk0[8];
};

__global__ void smsa_transpose_all_kernel(TrJobs J) {
    __shared__ float t[32][33];
    int bid = blockIdx.x;
    int j = 0;
#pragma unroll
    for (int i = 1; i < 8; i++)
        if (bid >= J.blk0[i]) j = i;
    int rel = bid - J.blk0[j];
    int K = J.K[j], N = J.N[j];
    int nbx = N >> 5;
    int n0 = (rel % nbx) * 32, k0 = (rel / nbx) * 32;
    const float* W = J.W[j];
    __nv_bfloat16* Wt = J.Wt[j];
    int tx = threadIdx.x, ty = threadIdx.y;
#pragma unroll
    for (int i = 0; i < 32; i += 8)
        t[ty + i][tx] = W[(size_t)(k0 + ty + i) * N + n0 + tx];
    __syncthreads();
#pragma unroll
    for (int i = 0; i < 32; i += 8)
        Wt[(size_t)(n0 + ty + i) * K + k0 + tx] = __float2bfloat16(t[tx][ty + i]);
}

// ---------------------------------------------------------------------------
// Segmented bf16 HMMA GEMM (R11 config; optional scattered C rows via scat=1)
// ---------------------------------------------------------------------------
__global__ __launch_bounds__(128, 2) void smsa_hgemm_kernel(
    const __nv_bfloat16* __restrict__ A, int lda,
    const __nv_bfloat16* __restrict__ Bt0, const __nv_bfloat16* __restrict__ Bt1,
    void* __restrict__ C0, void* __restrict__ C1, int ldc0, int ldc1,
    const float* __restrict__ bias0, const float* __restrict__ bias1,
    const float* __restrict__ res0, const float* __restrict__ res1, int ldr,
    int K, int act, int outbf, int mb1, int nbmax1, int scat) {
    extern __shared__ __align__(1024) char sm[];
    uint32_t sb = smem_u32(sm);
    const int tid = threadIdx.x;
    const int mb = blockIdx.y, nb = blockIdx.x;
    const int warp = tid >> 5, lane = tid & 31;
    const int wm = warp & 1, wn = warp >> 1;

    const int seg = (mb >= mb1);
    if (seg && nb >= nbmax1) return;
    const __nv_bfloat16* Bt = seg ? Bt1 : Bt0;
    const float* bias = seg ? bias1 : bias0;
    const float* res = seg ? res1 : res0;
    void* Cm = seg ? C1 : C0;
    const int ldc = seg ? ldc1 : ldc0;
    const int lrow0 = (seg ? (mb - mb1) : mb) * 128;

    const __nv_bfloat16* Ag = A + (size_t)(mb * 128) * lda;
    const __nv_bfloat16* Bg = Bt + (size_t)(nb * 128) * K;

    const int nch = K >> 6;
    auto copy_stage = [&](int c, int s) {
        uint32_t sbase = sb + (uint32_t)s * 32768u;
        const __nv_bfloat16* ga = Ag + c * 64;
        const __nv_bfloat16* gb = Bg + c * 64;
#pragma unroll
        for (int p = 0; p < 8; p++) {
            int u = p * 128 + tid;
            int row = u >> 3, c16 = u & 7;
            CP16(sbase + SWZ128((uint32_t)row * 128 + c16 * 16),
                 ga + (size_t)row * lda + c16 * 8);
        }
#pragma unroll
        for (int p = 0; p < 8; p++) {
            int u = p * 128 + tid;
            int row = u >> 3, c16 = u & 7;
            CP16(sbase + 16384u + SWZ128((uint32_t)row * 128 + c16 * 16),
                 gb + (size_t)row * K + c16 * 8);
        }
    };

    float acc[4][8][4];
#pragma unroll
    for (int mt = 0; mt < 4; mt++)
#pragma unroll
        for (int nt = 0; nt < 8; nt++)
#pragma unroll
            for (int q = 0; q < 4; q++) acc[mt][nt][q] = 0.0f;

    const int a_row = wm * 64 + (lane & 15);
    const int b_row = wn * 64 + (lane & 15);
    const int hi = lane >> 4;

    copy_stage(0, 0);
    CPCOMMIT();
    if (nch > 1) copy_stage(1, 1);
    CPCOMMIT();

    for (int c = 0; c < nch; c++) {
        CPWAIT1();
        __syncthreads();
        if (c + 2 < nch) copy_stage(c + 2, (c + 2) % 3);
        CPCOMMIT();

        uint32_t abase = sb + (uint32_t)(c % 3) * 32768u;
        uint32_t bbase = abase + 16384u;
#pragma unroll
        for (int j = 0; j < 4; j++) {
            uint32_t af[4][4], bf[4][4];
            int ch = 2 * j + hi;
#pragma unroll
            for (int mt = 0; mt < 4; mt++) {
                uint32_t ad = abase + SWZ128((uint32_t)(a_row + mt * 16) * 128 + ch * 16);
                LDSM_X4(af[mt], ad);
            }
#pragma unroll
            for (int bt = 0; bt < 4; bt++) {
                uint32_t bd = bbase + SWZ128((uint32_t)(b_row + bt * 16) * 128 + ch * 16);
                LDSM_X4(bf[bt], bd);
            }
#pragma unroll
            for (int mt = 0; mt < 4; mt++)
#pragma unroll
                for (int nt = 0; nt < 8; nt++)
                    MMA16816(acc[mt][nt], af[mt],
                             bf[nt >> 1][nt & 1], bf[nt >> 1][(nt & 1) + 2]);
        }
    }

    int qrow = lane >> 2, qcol = (lane & 3) * 2;
#pragma unroll
    for (int mt = 0; mt < 4; mt++)
#pragma unroll
        for (int half = 0; half < 2; half++) {
            int row = lrow0 + wm * 64 + mt * 16 + qrow + half * 8;
            int orow = scat ? scat_row(row) : row;
#pragma unroll
            for (int nt = 0; nt < 8; nt++) {
                int col = nb * 128 + wn * 64 + nt * 8 + qcol;
                float v0 = acc[mt][nt][half * 2 + 0];
                float v1 = acc[mt][nt][half * 2 + 1];
                if (bias) {
                    float2 bv = *(const float2*)(bias + col);
                    v0 += bv.x; v1 += bv.y;
                }
                if (res) {
                    float2 rr = *(const float2*)(res + (size_t)row * ldr + col);
                    v0 += rr.x; v1 += rr.y;
                }
                if (act) { v0 = gelu_exact(v0); v1 = gelu_exact(v1); }
                if (outbf) {
                    *(uint32_t*)((__nv_bfloat16*)Cm + (size_t)orow * ldc + col) =
                        bf2u(v0, v1);
                } else {
                    *(float2*)((float*)Cm + (size_t)orow * ldc + col) =
                        make_float2(v0, v1);
                }
            }
        }
}

// ---------------------------------------------------------------------------
// Fused HMMA flash attention (frozen since round 7)
// ---------------------------------------------------------------------------
__global__ __launch_bounds__(256) void smsa_fattn_kernel(
    const __nv_bfloat16* __restrict__ qkv, __nv_bfloat16* __restrict__ out) {
    extern __shared__ __align__(128) char smc[];
    uint32_t sbq = smem_u32(smc);
    const uint32_t Qs = sbq, Ks = sbq + 20480u, Vs = sbq + 40960u;
    int win = blockIdx.x >> 3, h = blockIdx.x & 7;
    int tid = threadIdx.x, lane = tid & 31, warp = tid >> 5;
    const __nv_bfloat16* base = qkv + (size_t)win * 256 * 768 + h * 32;

    {
        const uint4* qp = (const uint4*)(base + (size_t)tid * 768);
        const uint4* kp = (const uint4*)(base + (size_t)tid * 768 + 256);
        const uint4* vp = (const uint4*)(base + (size_t)tid * 768 + 512);
        uint32_t qd = Qs + tid * 80, kd = Ks + tid * 80, vd = Vs + tid * 80;
#pragma unroll
        for (int c = 0; c < 4; c++) {
            uint4 v;
            v = qp[c];
            asm volatile("st.shared.v4.b32 [%0], {%1,%2,%3,%4};"
                         :: "r"(qd + c * 16), "r"(v.x), "r"(v.y), "r"(v.z), "r"(v.w));
            v = kp[c];
            asm volatile("st.shared.v4.b32 [%0], {%1,%2,%3,%4};"
                         :: "r"(kd + c * 16), "r"(v.x), "r"(v.y), "r"(v.z), "r"(v.w));
            v = vp[c];
            asm volatile("st.shared.v4.b32 [%0], {%1,%2,%3,%4};"
                         :: "r"(vd + c * 16), "r"(v.x), "r"(v.y), "r"(v.z), "r"(v.w));
        }
    }
    __syncthreads();

    const int qb = warp * 32;
    uint32_t qf[2][2][4];
#pragma unroll
    for (int mt = 0; mt < 2; mt++)
#pragma unroll
        for (int kc = 0; kc < 2; kc++) {
            uint32_t ad = Qs + (uint32_t)(qb + mt * 16 + (lane & 15)) * 80
                          + (lane >> 4) * 16 + kc * 32;
            LDSM_X4(qf[mt][kc], ad);
        }

    float oacc[2][4][4];
#pragma unroll
    for (int mt = 0; mt < 2; mt++)
#pragma unroll
        for (int nt = 0; nt < 4; nt++)
#pragma unroll
            for (int q = 0; q < 4; q++) oacc[mt][nt][q] = 0.0f;
    float mrun[2][2] = {{-1e30f, -1e30f}, {-1e30f, -1e30f}};
    float lrun[2][2] = {{0.0f, 0.0f}, {0.0f, 0.0f}};
    const float C2 = 0.17677669529663687f * 1.4426950408889634f;

    for (int kb = 0; kb < 4; kb++) {
        float sacc[2][8][4];
#pragma unroll
        for (int mt = 0; mt < 2; mt++)
#pragma unroll
            for (int nt = 0; nt < 8; nt++)
#pragma unroll
                for (int q = 0; q < 4; q++) sacc[mt][nt][q] = 0.0f;

#pragma unroll
        for (int kc = 0; kc < 2; kc++) {
            uint32_t kf[4][4];
#pragma unroll
            for (int grp = 0; grp < 4; grp++) {
                uint32_t ad = Ks + (uint32_t)(kb * 64 + grp * 16 + (lane & 15)) * 80
                              + (lane >> 4) * 16 + kc * 32;
                LDSM_X4(kf[grp], ad);
            }
#pragma unroll
            for (int mt = 0; mt < 2; mt++)
#pragma unroll
                for (int nt = 0; nt < 8; nt++)
                    MMA16816(sacc[mt][nt], qf[mt][kc],
                             kf[nt >> 1][nt & 1], kf[nt >> 1][(nt & 1) + 2]);
        }

#pragma unroll
        for (int mt = 0; mt < 2; mt++)
#pragma unroll
            for (int hf = 0; hf < 2; hf++) {
                float mx = -1e30f;
#pragma unroll
                for (int nt = 0; nt < 8; nt++)
                    mx = fmaxf(mx, fmaxf(sacc[mt][nt][hf * 2], sacc[mt][nt][hf * 2 + 1]));
                mx = fmaxf(mx, __shfl_xor_sync(0xffffffffu, mx, 1));
                mx = fmaxf(mx, __shfl_xor_sync(0xffffffffu, mx, 2));
                float mold = mrun[mt][hf];
                float mnew = fmaxf(mold, mx);
                float corr = exp2f(C2 * (mold - mnew));
                mrun[mt][hf] = mnew;
                float sum = 0.0f;
#pragma unroll
                for (int nt = 0; nt < 8; nt++) {
                    float p0 = exp2f(C2 * (sacc[mt][nt][hf * 2] - mnew));
                    float p1 = exp2f(C2 * (sacc[mt][nt][hf * 2 + 1] - mnew));
                    sacc[mt][nt][hf * 2] = p0;
                    sacc[mt][nt][hf * 2 + 1] = p1;
                    sum += p0 + p1;
                }
                sum += __shfl_xor_sync(0xffffffffu, sum, 1);
                sum += __shfl_xor_sync(0xffffffffu, sum, 2);
                lrun[mt][hf] = lrun[mt][hf] * corr + sum;
#pragma unroll
                for (int nt = 0; nt < 4; nt++) {
                    oacc[mt][nt][hf * 2] *= corr;
                    oacc[mt][nt][hf * 2 + 1] *= corr;
                }
            }

#pragma unroll
        for (int kc4 = 0; kc4 < 4; kc4++) {
            uint32_t vf[2][4];
#pragma unroll
            for (int dg = 0; dg < 2; dg++) {
                uint32_t ad = Vs + (uint32_t)(kb * 64 + kc4 * 16 + (lane & 15)) * 80
                              + dg * 32 + (lane >> 4) * 16;
                LDSM_X4T(vf[dg], ad);
            }
#pragma unroll
            for (int mt = 0; mt < 2; mt++) {
                uint32_t a[4];
                a[0] = bf2u(sacc[mt][2 * kc4][0], sacc[mt][2 * kc4][1]);
                a[1] = bf2u(sacc[mt][2 * kc4][2], sacc[mt][2 * kc4][3]);
                a[2] = bf2u(sacc[mt][2 * kc4 + 1][0], sacc[mt][2 * kc4 + 1][1]);
                a[3] = bf2u(sacc[mt][2 * kc4 + 1][2], sacc[mt][2 * kc4 + 1][3]);
#pragma unroll
                for (int nt = 0; nt < 4; nt++)
                    MMA16816(oacc[mt][nt], a,
                             vf[nt >> 1][(nt & 1) * 2], vf[nt >> 1][(nt & 1) * 2 + 1]);
            }
        }
    }

#pragma unroll
    for (int mt = 0; mt < 2; mt++) {
        float inv0 = 1.0f / lrun[mt][0];
        float inv1 = 1.0f / lrun[mt][1];
        int row0 = win * 256 + qb + mt * 16 + (lane >> 2);
        int col = h * 32 + (lane & 3) * 2;
#pragma unroll
        for (int nt = 0; nt < 4; nt++) {
            *(uint32_t*)(out + (size_t)row0 * 256 + col + nt * 8) =
                bf2u(oacc[mt][nt][0] * inv0, oacc[mt][nt][1] * inv0);
            *(uint32_t*)(out + (size_t)(row0 + 8) * 256 + col + nt * 8) =
                bf2u(oacc[mt][nt][2] * inv1, oacc[mt][nt][3] * inv1);
        }
    }
}

// ---------------------------------------------------------------------------
__global__ __launch_bounds__(256) void smsa_xattn_kernel(
    const __nv_bfloat16* __restrict__ Q, const __nv_bfloat16* __restrict__ KV,
    __nv_bfloat16* __restrict__ AO) {
    int f = blockIdx.x;
    int h = threadIdx.x >> 5;
    int d = threadIdx.x & 31;
    int b = f >> 10, hh = (f >> 7) & 7, w = (f >> 4) & 7;
    int r1 = (f >> 2) & 3, r2 = f & 3;
    int fw = (b * 8 + hh) * 8 + w;
    int base_t = r1 * 64 + r2 * 4;
    float qd = __bfloat162float(Q[(size_t)f * 256 + h * 32 + d]);
    const float sc = 0.17677669529663687f;
    float s[16];
#pragma unroll
    for (int j = 0; j < 16; j++) {
        int t = base_t + (j >> 2) * 16 + (j & 3);
        float kd = __bfloat162float(KV[((size_t)(fw * 256 + t)) * 512 + h * 32 + d]);
        float pr = qd * kd;
#pragma unroll
        for (int o = 16; o > 0; o >>= 1)
            pr += __shfl_xor_sync(0xffffffffu, pr, o);
        s[j] = pr * sc;
    }
    float m = s[0];
#pragma unroll
    for (int j = 1; j < 16; j++) m = fmaxf(m, s[j]);
    float l = 0.0f, p[16];
#pragma unroll
    for (int j = 0; j < 16; j++) {
        p[j] = __expf(s[j] - m);
        l += p[j];
    }
    float inv = 1.0f / l;
    float acc = 0.0f;
#pragma unroll
    for (int j = 0; j < 16; j++) {
        int t = base_t + (j >> 2) * 16 + (j & 3);
        acc = fmaf(p[j], __bfloat162float(
                        KV[((size_t)(fw * 256 + t)) * 512 + 256 + h * 32 + d]),
                   acc);
    }
    AO[(size_t)f * 256 + h * 32 + d] = __float2bfloat16(acc * inv);
}

// ---------------------------------------------------------------------------
// Host side
// ---------------------------------------------------------------------------
static void run_hgemm_seg(const __nv_bfloat16* A, int lda,
                          const __nv_bfloat16* Bt0, const __nv_bfloat16* Bt1,
                          void* C0, void* C1, int ldc0, int ldc1,
                          const float* bias0, const float* bias1,
                          const float* res0, const float* res1, int ldr,
                          int M, int N, int K, int act, int outbf,
                          int mb1, int nbmax1, int scat = 0) {
    dim3 grid(N / 128, M / 128);
    smsa_hgemm_kernel<<<grid, 128, GEMM_SMEM>>>(
        A, lda, Bt0, Bt1, C0, C1, ldc0, ldc1, bias0, bias1,
        res0, res1, ldr, K, act, outbf, mb1, nbmax1, scat);
}

static void run_hgemm(const __nv_bfloat16* A, int lda, const __nv_bfloat16* Bt,
                      void* Cm, int ldc, const float* bias,
                      const float* res, int ldr, int M, int N, int K,
                      int act, int outbf, int scat = 0) {
    run_hgemm_seg(A, lda, Bt, Bt, Cm, Cm, ldc, ldc, bias, bias, res, res, ldr,
                  M, N, K, act, outbf, 1 << 30, 1 << 30, scat);
}

static void run_ln2(const float* x, __nv_bfloat16* y,
                    const float* g0, const float* b0,
                    const float* g1, const float* b1, int ntok, int bnd) {
    smsa_ln_kernel<<<ntok / 8, 256>>>(x, y, g0, b0, g1, b1, bnd);
}

extern "C" void kernel_launch(void* const* d_in, const int* in_sizes, int n_in,
                              void* d_out, int out_size) {
    const float* scale0 = (const float*)d_in[0];
    const float* scale1 = (const float*)d_in[1];
    const float* pe_w1 = (const float*)d_in[2];
    const float* pe_b1 = (const float*)d_in[3];
    const float* pe_w2 = (const float*)d_in[4];
    const float* ln1_g = (const float*)d_in[5];
    const float* ln1_b = (const float*)d_in[6];
    const float* wqkv = (const float*)d_in[7];
    const float* bqkv = (const float*)d_in[8];
    const float* wo = (const float*)d_in[9];
    const float* bo = (const float*)d_in[10];
    const float* ln2_g = (const float*)d_in[11];
    const float* ln2_b = (const float*)d_in[12];
    const float* mw1 = (const float*)d_in[13];
    const float* mb1 = (const float*)d_in[14];
    const float* mw2 = (const float*)d_in[15];
    const float* mb2 = (const float*)d_in[16];
    float* out = (float*)d_out;
    float* out0 = out;
    float* out1 = out + (size_t)65536 * 256;

    float *X, *PE, *G;
    __nv_bfloat16 *Hb, *QKVb, *Tb, *WT;
    cudaGetSymbolAddress((void**)&X, g_X);
    cudaGetSymbolAddress((void**)&PE, g_PE);
    cudaGetSymbolAddress((void**)&G, g_G);
    cudaGetSymbolAddress((void**)&Hb, g_Hb);
    cudaGetSymbolAddress((void**)&QKVb, g_QKVb);
    cudaGetSymbolAddress((void**)&Tb, g_Tb);
    cudaGetSymbolAddress((void**)&WT, g_WT);
    float* X1 = X + (size_t)65536 * 256;

    cudaFuncSetAttribute(smsa_fattn_kernel,
                         cudaFuncAttributeMaxDynamicSharedMemorySize, ATTN_SMEM);
    cudaFuncSetAttribute(smsa_hgemm_kernel,
                         cudaFuncAttributeMaxDynamicSharedMemorySize, GEMM_SMEM);

    const __nv_bfloat16 *wqkvT0 = WT + 0, *woT0 = WT + 196608;
    const __nv_bfloat16 *w1T0 = WT + 262144, *w2T0 = WT + 524288;
    const __nv_bfloat16 *wqkvT1 = WT + 786432, *woT1 = WT + 983040;
    const __nv_bfloat16 *w1T1 = WT + 1048576, *w2T1 = WT + 1310720;
    const float *ln1g0 = ln1_g, *ln1b0 = ln1_b;
    const float *ln2g0 = ln2_g, *ln2b0 = ln2_b;
    const float *ln1g1 = ln1_g + 256, *ln1b1 = ln1_b + 256;
    const float *ln2g1 = ln2_g + 256, *ln2b1 = ln2_b + 256;

    // 0) weight transposes, one launch
    {
        TrJobs J;
        const float* Ws[8] = {wqkv, wqkv + 196608, wo, wo + 65536,
                              mw1, mw1 + 262144, mw2, mw2 + 262144};
        __nv_bfloat16* Wts[8] = {WT + 0, WT + 786432, WT + 196608, WT + 983040,
                                 WT + 262144, WT + 1048576, WT + 524288, WT + 1310720};
        int Ks[8] = {256, 256, 256, 256, 256, 256, 1024, 1024};
        int Ns[8] = {768, 768, 256, 256, 1024, 1024, 256, 256};
        int b0 = 0;
        for (int i = 0; i < 8; i++) {
            J.W[i] = Ws[i]; J.Wt[i] = Wts[i]; J.K[i] = Ks[i]; J.N[i] = Ns[i];
            J.blk0[i] = b0;
            b0 += (Ks[i] / 32) * (Ns[i] / 32);
        }
        smsa_transpose_all_kernel<<<b0, dim3(32, 8)>>>(J);
    }

    // 1) position embeddings; scale0 add+LN1 fused
    smsa_posemb_kernel<<<dim3(256, 2), 256>>>(pe_w1, pe_b1, pe_w2, PE);
    smsa_add_pe_ln_kernel<<<8192, 256>>>(scale0, PE, X, Hb, ln1g0, ln1b0);

    // 2) add_pe(scale1) + pool + LN1(scale1) fused -> X1, Hb rows 65536+
    smsa_pool_ln_kernel<<<4096, 256>>>(X, scale1, PE + 65536, X1,
                                       Hb + (size_t)65536 * 256, ln1g1, ln1b1);

    // 3) MERGED sattn chain over 69632 rows
    run_hgemm_seg(Hb, 256, wqkvT0, wqkvT1,
                  QKVb, QKVb + (size_t)65536 * 768, 768, 768,
                  bqkv, bqkv + 768, nullptr, nullptr, 0,
                  NTOKA, 768, 256, 0, 1, MB1T, 6);
    smsa_fattn_kernel<<<(NTOKA / 256) * 8, 256, ATTN_SMEM>>>(QKVb, Hb);
    run_hgemm_seg(Hb, 256, woT0, woT1,
                  X, X1, 256, 256,
                  bo, bo + 256, X, X1, 256,
                  NTOKA, 256, 256, 0, 0, MB1T, 2);
    run_ln2(X, Hb, ln2g0, ln2b0, ln2g1, ln2b1, NTOKA, NTOK0);
    run_hgemm_seg(Hb, 256, w1T0, w1T1,
                  Tb, Tb + (size_t)65536 * 1024, 1024, 1024,
                  mb1, mb1 + 1024, nullptr, nullptr, 0,
                  NTOKA, 1024, 256, 1, 1, MB1T, 8);
    run_hgemm_seg(Tb, 1024, w2T0, w2T1,
                  out0, X1, 256, 256,
                  mb2, mb2 + 256, X, X1, 256,
                  NTOKA, 256, 1024, 0, 0, MB1T, 2);

    // cross kn LN: out0 -> Hb rows 0..65535
    run_ln2(out0, Hb, ln1g1, ln1b1, ln1g1, ln1b1, NTOK0, NTOK0);
    // gather + LN(G) -> G fp32, Hb rows 65536+ (bf16 qn)
    smsa_gather_ln_kernel<<<512, 256>>>(X1, G, Hb + (size_t)65536 * 256,
                                        ln1g1, ln1b1);

    __nv_bfloat16* Sqb = Tb;
    __nv_bfloat16* AOb = Tb + (size_t)4096 * 256;
    __nv_bfloat16* Sgb = Tb + (size_t)2 * 4096 * 256;
    __nv_bfloat16* Thb = Tb + (size_t)3 * 4096 * 256;

    // 4) segmented: seg0 = cross K|V (65536 x 512), seg1 = Sq (4096 x 256)
    run_hgemm_seg(Hb, 256, wqkvT1 + 256 * 256, wqkvT1,
                  QKVb, Sqb, 512, 256,
                  bqkv + 768 + 256, bqkv + 768, nullptr, nullptr, 0,
                  NTOKA, 512, 256, 0, 1, MB1T, 2);

    smsa_xattn_kernel<<<4096, 256>>>(Sqb, QKVb, AOb);
    run_hgemm(AOb, 256, woT1, G, 256, bo + 256, G, 256, NTOK1, 256, 256, 0, 0);
    run_ln2(G, Sgb, ln2g1, ln2b1, ln2g1, ln2b1, NTOK1, NTOK1);
    run_hgemm(Sgb, 256, w1T1, Thb, 1024, mb1 + 1024, nullptr, 0,
              NTOK1, 1024, 256, 1, 1);
    // final small GEMM writes DIRECTLY scattered into out1 (scat=1)
    run_hgemm(Thb, 1024, w2T1, out1, 256, mb2 + 256, G, 256,
              NTOK1, 256, 1024, 0, 0, 1);
}

// round 13
// speedup vs baseline: 1.0505x; 1.0505x over previous
#include <cuda_runtime.h>
#include <cuda_bf16.h>
#include <math.h>
#include <stdint.h>

// ---------------------------------------------------------------------------
// StackMSA round 13: R11 structure restored (unmodified GEMM body, standalone
// scatter) + the one verified-positive R12 change (add_pe(scale1) fused into
// pool+LN). GEMM/attention frozen at HMMA pipe floor.
// ---------------------------------------------------------------------------

#define NTOK0 65536
#define NTOK1 4096
#define NTOKA 69632
#define MB1T 512
#define ATTN_SMEM 61440
#define GEMM_SMEM 98304     // 3 stages x (16KB A + 16KB B)

__device__ float g_X[69632 * 256];
__device__ float g_PE[2 * 256 * 256];
__device__ float g_G[4096 * 256];
__device__ __nv_bfloat16 g_Hb[69632 * 256];
__device__ __nv_bfloat16 g_QKVb[69632 * 768];
__device__ __nv_bfloat16 g_Tb[69632 * 1024];
__device__ __nv_bfloat16 g_WT[1572864];

__device__ __forceinline__ float gelu_exact(float x) {
    return 0.5f * x * (1.0f + erff(x * 0.70710678118654752f));
}

__device__ __forceinline__ uint32_t smem_u32(const void* p) {
    uint32_t a;
    asm("{ .reg .u64 t; cvta.to.shared.u64 t, %1; cvt.u32.u64 %0, t; }"
        : "=r"(a) : "l"(p));
    return a;
}

#define SWZ128(o) ((o) ^ (((o) >> 3) & 0x70))
#define CP16(dst, src) \
    asm volatile("cp.async.cg.shared.global [%0], [%1], 16;" :: "r"(dst), "l"(src))
#define CPCOMMIT() asm volatile("cp.async.commit_group;" ::: "memory")
#define CPWAIT1() asm volatile("cp.async.wait_group 1;" ::: "memory")

#define LDSM_X4(r, addr) \
    asm volatile("ldmatrix.sync.aligned.m8n8.x4.shared.b16 {%0,%1,%2,%3}, [%4];" \
                 : "=r"((r)[0]), "=r"((r)[1]), "=r"((r)[2]), "=r"((r)[3]) : "r"(addr))
#define LDSM_X4T(r, addr) \
    asm volatile("ldmatrix.sync.aligned.m8n8.x4.trans.shared.b16 {%0,%1,%2,%3}, [%4];" \
                 : "=r"((r)[0]), "=r"((r)[1]), "=r"((r)[2]), "=r"((r)[3]) : "r"(addr))
#define MMA16816(d, a, b0, b1) \
    asm volatile("mma.sync.aligned.m16n8k16.row.col.f32.bf16.bf16.f32 " \
                 "{%0,%1,%2,%3}, {%4,%5,%6,%7}, {%8,%9}, {%0,%1,%2,%3};" \
                 : "+f"((d)[0]), "+f"((d)[1]), "+f"((d)[2]), "+f"((d)[3]) \
                 : "r"((a)[0]), "r"((a)[1]), "r"((a)[2]), "r"((a)[3]), \
                   "r"(b0), "r"(b1))

__device__ __forceinline__ uint32_t bf2u(float x, float y) {
    __nv_bfloat162 h = __float22bfloat162_rn(make_float2(x, y));
    return *(uint32_t*)&h;
}

// ---------------------------------------------------------------------------
__global__ void smsa_posemb_kernel(const float* __restrict__ w1,
                                   const float* __restrict__ b1,
                                   const float* __restrict__ w2,
                                   float* __restrict__ pe) {
    int t = blockIdx.x, s = blockIdx.y, tid = threadIdx.x;
    __shared__ float hid[512];
    float c0 = (float)((t >> 4) - 8) * 0.125f;
    float c1 = (float)((t & 15) - 8) * 0.125f;
    const float* W1 = w1 + s * 1024;
    const float* B1 = b1 + s * 512;
    for (int k = tid; k < 512; k += 256)
        hid[k] = fmaxf(fmaf(c0, W1[k], fmaf(c1, W1[512 + k], B1[k])), 0.0f);
    __syncthreads();
    const float* W2 = w2 + s * 512 * 256;
    float acc = 0.0f;
#pragma unroll 8
    for (int k = 0; k < 512; k++) acc = fmaf(hid[k], W2[k * 256 + tid], acc);
    pe[s * 65536 + t * 256 + tid] = acc;
}

__global__ __launch_bounds__(256) void smsa_add_pe_ln_kernel(
    const float* __restrict__ x, const float* __restrict__ pe,
    float* __restrict__ y, __nv_bfloat16* __restrict__ hb,
    const float* __restrict__ gg, const float* __restrict__ bb) {
    int tok = blockIdx.x * 8 + (threadIdx.x >> 5);
    int lane = threadIdx.x & 31;
    const float4* xr = (const float4*)(x + (size_t)tok * 256);
    const float4* pr = (const float4*)(pe + (size_t)(tok & 255) * 256);
    float4 v0 = xr[lane], v1 = xr[lane + 32];
    float4 p0 = pr[lane], p1 = pr[lane + 32];
    v0.x += p0.x; v0.y += p0.y; v0.z += p0.z; v0.w += p0.w;
    v1.x += p1.x; v1.y += p1.y; v1.z += p1.z; v1.w += p1.w;
    float4* yr = (float4*)(y + (size_t)tok * 256);
    yr[lane] = v0;
    yr[lane + 32] = v1;
    float s = v0.x + v0.y + v0.z + v0.w + v1.x + v1.y + v1.z + v1.w;
    float ss = v0.x * v0.x + v0.y * v0.y + v0.z * v0.z + v0.w * v0.w +
               v1.x * v1.x + v1.y * v1.y + v1.z * v1.z + v1.w * v1.w;
#pragma unroll
    for (int o = 16; o > 0; o >>= 1) {
        s += __shfl_xor_sync(0xffffffffu, s, o);
        ss += __shfl_xor_sync(0xffffffffu, ss, o);
    }
    float mean = s * 0.00390625f;
    float var = ss * 0.00390625f - mean * mean;
    float rstd = rsqrtf(var + 1e-5f);
    float4 g0 = ((const float4*)gg)[lane], g1 = ((const float4*)gg)[lane + 32];
    float4 b0 = ((const float4*)bb)[lane], b1 = ((const float4*)bb)[lane + 32];
    uint2 o0, o1;
    o0.x = bf2u((v0.x - mean) * rstd * g0.x + b0.x, (v0.y - mean) * rstd * g0.y + b0.y);
    o0.y = bf2u((v0.z - mean) * rstd * g0.z + b0.z, (v0.w - mean) * rstd * g0.w + b0.w);
    o1.x = bf2u((v1.x - mean) * rstd * g1.x + b1.x, (v1.y - mean) * rstd * g1.y + b1.y);
    o1.y = bf2u((v1.z - mean) * rstd * g1.z + b1.z, (v1.w - mean) * rstd * g1.w + b1.w);
    uint2* hr = (uint2*)(hb + (size_t)tok * 256);
    hr[lane] = o0;
    hr[lane + 32] = o1;
}

// fused add_pe(scale1) + pool + LN1(scale1): v = (scale1 + pe) + max
__global__ __launch_bounds__(256) void smsa_pool_ln_kernel(
    const float* __restrict__ x0, const float* __restrict__ scale1,
    const float* __restrict__ pe1, float* __restrict__ x1,
    __nv_bfloat16* __restrict__ hb1,
    const float* __restrict__ gg, const float* __restrict__ bb) {
    __shared__ float red[16];
    int gid = blockIdx.x, c = threadIdx.x;
    int b = gid >> 10, gr = (gid >> 5) & 31, gc = gid & 31;
    int h = gr >> 2, r1 = gr & 3, w = gc >> 2, r2 = gc & 3;
    int fw = (b * 8 + h) * 8 + w;
    const float* base = x0 + ((size_t)fw * 256 + r1 * 64 + r2 * 4) * 256 + c;
    float m = -1e30f;
#pragma unroll
    for (int p1 = 0; p1 < 4; p1++)
#pragma unroll
        for (int p2 = 0; p2 < 4; p2++)
            m = fmaxf(m, base[(p1 * 16 + p2) * 256]);
    int gwin = b * 4 + (gr >> 4) * 2 + (gc >> 4);
    int tt = (gr & 15) * 16 + (gc & 15);
    size_t idx = ((size_t)gwin * 256 + tt) * 256 + c;
    float v = (scale1[idx] + pe1[(size_t)tt * 256 + c]) + m;
    x1[idx] = v;
    float s = v, q = v * v;
#pragma unroll
    for (int o = 16; o > 0; o >>= 1) {
        s += __shfl_xor_sync(0xffffffffu, s, o);
        q += __shfl_xor_sync(0xffffffffu, q, o);
    }
    int warp = c >> 5, lane = c & 31;
    if (lane == 0) { red[warp] = s; red[warp + 8] = q; }
    __syncthreads();
    float S = 0.0f, Q = 0.0f;
#pragma unroll
    for (int wi = 0; wi < 8; wi++) { S += red[wi]; Q += red[wi + 8]; }
    float mean = S * 0.00390625f;
    float var = Q * 0.00390625f - mean * mean;
    float rstd = rsqrtf(var + 1e-5f);
    hb1[idx] = __float2bfloat16((v - mean) * rstd * gg[c] + bb[c]);
}

// LayerNorm, segmented params
__global__ __launch_bounds__(256) void smsa_ln_kernel(
    const float* __restrict__ x, __nv_bfloat16* __restrict__ y,
    const float* __restrict__ gg0, const float* __restrict__ bb0,
    const float* __restrict__ gg1, const float* __restrict__ bb1, int bnd) {
    int tok = blockIdx.x * 8 + (threadIdx.x >> 5);
    int lane = threadIdx.x & 31;
    const float* gg = tok < bnd ? gg0 : gg1;
    const float* bb = tok < bnd ? bb0 : bb1;
    const float4* row = (const float4*)(x + (size_t)tok * 256);
    float4 v0 = row[lane], v1 = row[lane + 32];
    float s = v0.x + v0.y + v0.z + v0.w + v1.x + v1.y + v1.z + v1.w;
    float ss = v0.x * v0.x + v0.y * v0.y + v0.z * v0.z + v0.w * v0.w +
               v1.x * v1.x + v1.y * v1.y + v1.z * v1.z + v1.w * v1.w;
#pragma unroll
    for (int o = 16; o > 0; o >>= 1) {
        s += __shfl_xor_sync(0xffffffffu, s, o);
        ss += __shfl_xor_sync(0xffffffffu, ss, o);
    }
    float mean = s * 0.00390625f;
    float var = ss * 0.00390625f - mean * mean;
    float rstd = rsqrtf(var + 1e-5f);
    float4 g0 = ((const float4*)gg)[lane], g1 = ((const float4*)gg)[lane + 32];
    float4 b0 = ((const float4*)bb)[lane], b1 = ((const float4*)bb)[lane + 32];
    uint2 o0, o1;
    o0.x = bf2u((v0.x - mean) * rstd * g0.x + b0.x, (v0.y - mean) * rstd * g0.y + b0.y);
    o0.y = bf2u((v0.z - mean) * rstd * g0.z + b0.z, (v0.w - mean) * rstd * g0.w + b0.w);
    o1.x = bf2u((v1.x - mean) * rstd * g1.x + b1.x, (v1.y - mean) * rstd * g1.y + b1.y);
    o1.y = bf2u((v1.z - mean) * rstd * g1.z + b1.z, (v1.w - mean) * rstd * g1.w + b1.w);
    uint2* yr = (uint2*)(y + (size_t)tok * 256);
    yr[lane] = o0;
    yr[lane + 32] = o1;
}

// fused gather + LN
__global__ __launch_bounds__(256) void smsa_gather_ln_kernel(
    const float* __restrict__ x1, float* __restrict__ g,
    __nv_bfloat16* __restrict__ hbo,
    const float* __restrict__ gg, const float* __restrict__ bb) {
    int f = blockIdx.x * 8 + (threadIdx.x >> 5);
    int lane = threadIdx.x & 31;
    int b = f >> 10, h = (f >> 7) & 7, w = (f >> 4) & 7;
    int r1 = (f >> 2) & 3, r2 = f & 3;
    int gr = h * 4 + r1, gc = w * 4 + r2;
    int gwin = b * 4 + (gr >> 4) * 2 + (gc >> 4);
    int tt = (gr & 15) * 16 + (gc & 15);
    const float4* row = (const float4*)(x1 + ((size_t)gwin * 256 + tt) * 256);
    float4 v0 = row[lane], v1 = row[lane + 32];
    float4* grow = (float4*)(g + (size_t)f * 256);
    grow[lane] = v0;
    grow[lane + 32] = v1;
    float s = v0.x + v0.y + v0.z + v0.w + v1.x + v1.y + v1.z + v1.w;
    float ss = v0.x * v0.x + v0.y * v0.y + v0.z * v0.z + v0.w * v0.w +
               v1.x * v1.x + v1.y * v1.y + v1.z * v1.z + v1.w * v1.w;
#pragma unroll
    for (int o = 16; o > 0; o >>= 1) {
        s += __shfl_xor_sync(0xffffffffu, s, o);
        ss += __shfl_xor_sync(0xffffffffu, ss, o);
    }
    float mean = s * 0.00390625f;
    float var = ss * 0.00390625f - mean * mean;
    float rstd = rsqrtf(var + 1e-5f);
    float4 g0 = ((const float4*)gg)[lane], g1 = ((const float4*)gg)[lane + 32];
    float4 b0 = ((const float4*)bb)[lane], b1 = ((const float4*)bb)[lane + 32];
    uint2 o0, o1;
    o0.x = bf2u((v0.x - mean) * rstd * g0.x + b0.x, (v0.y - mean) * rstd * g0.y + b0.y);
    o0.y = bf2u((v0.z - mean) * rstd * g0.z + b0.z, (v0.w - mean) * rstd * g0.w + b0.w);
    o1.x = bf2u((v1.x - mean) * rstd * g1.x + b1.x, (v1.y - mean) * rstd * g1.y + b1.y);
    o1.y = bf2u((v1.z - mean) * rstd * g1.z + b1.z, (v1.w - mean) * rstd * g1.w + b1.w);
    uint2* hr = (uint2*)(hbo + (size_t)f * 256);
    hr[lane] = o0;
    hr[lane + 32] = o1;
}

// ---------------------------------------------------------------------------
struct TrJobs {
    const float* W[8];
    __nv_bfloat16* Wt[8];
    int K[8], N[8], blk0[8];
};

__global__ void smsa_transpose_all_kernel(TrJobs J) {
    __shared__ float t[32][33];
    int bid = blockIdx.x;
    int j = 0;
#pragma unroll
    for (int i = 1; i < 8; i++)
        if (bid >= J.blk0[i]) j = i;
    int rel = bid - J.blk0[j];
    int K = J.K[j], N = J.N[j];
    int nbx = N >> 5;
    int n0 = (rel % nbx) * 32, k0 = (rel / nbx) * 32;
    const float* W = J.W[j];
    __nv_bfloat16* Wt = J.Wt[j];
    int tx = threadIdx.x, ty = threadIdx.y;
#pragma unroll
    for (int i = 0; i < 32; i += 8)
        t[ty + i][tx] = W[(size_t)(k0 + ty + i) * N + n0 + tx];
    __syncthreads();
#pragma unroll
    for (int i = 0; i < 32; i += 8)
        Wt[(size_t)(n0 + ty + i) * K + k0 + tx] = __float2bfloat16(t[tx][ty + i]);
}

// ---------------------------------------------------------------------------
// Segmented bf16 HMMA GEMM — byte-identical to the round-11 (848.9us) body.
// ---------------------------------------------------------------------------
__global__ __launch_bounds__(128, 2) void smsa_hgemm_kernel(
    const __nv_bfloat16* __restrict__ A, int lda,
    const __nv_bfloat16* __restrict__ Bt0, const __nv_bfloat16* __restrict__ Bt1,
    void* __restrict__ C0, void* __restrict__ C1, int ldc0, int ldc1,
    const float* __restrict__ bias0, const float* __restrict__ bias1,
    const float* __restrict__ res0, const float* __restrict__ res1, int ldr,
    int K, int act, int outbf, int mb1, int nbmax1) {
    extern __shared__ __align__(1024) char sm[];
    uint32_t sb = smem_u32(sm);
    const int tid = threadIdx.x;
    const int mb = blockIdx.y, nb = blockIdx.x;
    const int warp = tid >> 5, lane = tid & 31;
    const int wm = warp & 1, wn = warp >> 1;

    const int seg = (mb >= mb1);
    if (seg && nb >= nbmax1) return;
    const __nv_bfloat16* Bt = seg ? Bt1 : Bt0;
    const float* bias = seg ? bias1 : bias0;
    const float* res = seg ? res1 : res0;
    void* Cm = seg ? C1 : C0;
    const int ldc = seg ? ldc1 : ldc0;
    const int lrow0 = (seg ? (mb - mb1) : mb) * 128;

    const __nv_bfloat16* Ag = A + (size_t)(mb * 128) * lda;
    const __nv_bfloat16* Bg = Bt + (size_t)(nb * 128) * K;

    const int nch = K >> 6;
    auto copy_stage = [&](int c, int s) {
        uint32_t sbase = sb + (uint32_t)s * 32768u;
        const __nv_bfloat16* ga = Ag + c * 64;
        const __nv_bfloat16* gb = Bg + c * 64;
#pragma unroll
        for (int p = 0; p < 8; p++) {
            int u = p * 128 + tid;
            int row = u >> 3, c16 = u & 7;
            CP16(sbase + SWZ128((uint32_t)row * 128 + c16 * 16),
                 ga + (size_t)row * lda + c16 * 8);
        }
#pragma unroll
        for (int p = 0; p < 8; p++) {
            int u = p * 128 + tid;
            int row = u >> 3, c16 = u & 7;
            CP16(sbase + 16384u + SWZ128((uint32_t)row * 128 + c16 * 16),
                 gb + (size_t)row * K + c16 * 8);
        }
    };

    float acc[4][8][4];
#pragma unroll
    for (int mt = 0; mt < 4; mt++)
#pragma unroll
        for (int nt = 0; nt < 8; nt++)
#pragma unroll
            for (int q = 0; q < 4; q++) acc[mt][nt][q] = 0.0f;

    const int a_row = wm * 64 + (lane & 15);
    const int b_row = wn * 64 + (lane & 15);
    const int hi = lane >> 4;

    copy_stage(0, 0);
    CPCOMMIT();
    if (nch > 1) copy_stage(1, 1);
    CPCOMMIT();

    for (int c = 0; c < nch; c++) {
        CPWAIT1();
        __syncthreads();
        if (c + 2 < nch) copy_stage(c + 2, (c + 2) % 3);
        CPCOMMIT();

        uint32_t abase = sb + (uint32_t)(c % 3) * 32768u;
        uint32_t bbase = abase + 16384u;
#pragma unroll
        for (int j = 0; j < 4; j++) {
            uint32_t af[4][4], bf[4][4];
            int ch = 2 * j + hi;
#pragma unroll
            for (int mt = 0; mt < 4; mt++) {
                uint32_t ad = abase + SWZ128((uint32_t)(a_row + mt * 16) * 128 + ch * 16);
                LDSM_X4(af[mt], ad);
            }
#pragma unroll
            for (int bt = 0; bt < 4; bt++) {
                uint32_t bd = bbase + SWZ128((uint32_t)(b_row + bt * 16) * 128 + ch * 16);
                LDSM_X4(bf[bt], bd);
            }
#pragma unroll
            for (int mt = 0; mt < 4; mt++)
#pragma unroll
                for (int nt = 0; nt < 8; nt++)
                    MMA16816(acc[mt][nt], af[mt],
                             bf[nt >> 1][nt & 1], bf[nt >> 1][(nt & 1) + 2]);
        }
    }

    int qrow = lane >> 2, qcol = (lane & 3) * 2;
#pragma unroll
    for (int mt = 0; mt < 4; mt++)
#pragma unroll
        for (int half = 0; half < 2; half++) {
            int row = lrow0 + wm * 64 + mt * 16 + qrow + half * 8;
#pragma unroll
            for (int nt = 0; nt < 8; nt++) {
                int col = nb * 128 + wn * 64 + nt * 8 + qcol;
                float v0 = acc[mt][nt][half * 2 + 0];
                float v1 = acc[mt][nt][half * 2 + 1];
                if (bias) {
                    float2 bv = *(const float2*)(bias + col);
                    v0 += bv.x; v1 += bv.y;
                }
                if (res) {
                    float2 rr = *(const float2*)(res + (size_t)row * ldr + col);
                    v0 += rr.x; v1 += rr.y;
                }
                if (act) { v0 = gelu_exact(v0); v1 = gelu_exact(v1); }
                if (outbf) {
                    *(uint32_t*)((__nv_bfloat16*)Cm + (size_t)row * ldc + col) =
                        bf2u(v0, v1);
                } else {
                    *(float2*)((float*)Cm + (size_t)row * ldc + col) =
                        make_float2(v0, v1);
                }
            }
        }
}

// ---------------------------------------------------------------------------
// Fused HMMA flash attention (frozen since round 7)
// ---------------------------------------------------------------------------
__global__ __launch_bounds__(256) void smsa_fattn_kernel(
    const __nv_bfloat16* __restrict__ qkv, __nv_bfloat16* __restrict__ out) {
    extern __shared__ __align__(128) char smc[];
    uint32_t sbq = smem_u32(smc);
    const uint32_t Qs = sbq, Ks = sbq + 20480u, Vs = sbq + 40960u;
    int win = blockIdx.x >> 3, h = blockIdx.x & 7;
    int tid = threadIdx.x, lane = tid & 31, warp = tid >> 5;
    const __nv_bfloat16* base = qkv + (size_t)win * 256 * 768 + h * 32;

    {
        const uint4* qp = (const uint4*)(base + (size_t)tid * 768);
        const uint4* kp = (const uint4*)(base + (size_t)tid * 768 + 256);
        const uint4* vp = (const uint4*)(base + (size_t)tid * 768 + 512);
        uint32_t qd = Qs + tid * 80, kd = Ks + tid * 80, vd = Vs + tid * 80;
#pragma unroll
        for (int c = 0; c < 4; c++) {
            uint4 v;
            v = qp[c];
            asm volatile("st.shared.v4.b32 [%0], {%1,%2,%3,%4};"
                         :: "r"(qd + c * 16), "r"(v.x), "r"(v.y), "r"(v.z), "r"(v.w));
            v = kp[c];
            asm volatile("st.shared.v4.b32 [%0], {%1,%2,%3,%4};"
                         :: "r"(kd + c * 16), "r"(v.x), "r"(v.y), "r"(v.z), "r"(v.w));
            v = vp[c];
            asm volatile("st.shared.v4.b32 [%0], {%1,%2,%3,%4};"
                         :: "r"(vd + c * 16), "r"(v.x), "r"(v.y), "r"(v.z), "r"(v.w));
        }
    }
    __syncthreads();

    const int qb = warp * 32;
    uint32_t qf[2][2][4];
#pragma unroll
    for (int mt = 0; mt < 2; mt++)
#pragma unroll
        for (int kc = 0; kc < 2; kc++) {
            uint32_t ad = Qs + (uint32_t)(qb + mt * 16 + (lane & 15)) * 80
                          + (lane >> 4) * 16 + kc * 32;
            LDSM_X4(qf[mt][kc], ad);
        }

    float oacc[2][4][4];
#pragma unroll
    for (int mt = 0; mt < 2; mt++)
#pragma unroll
        for (int nt = 0; nt < 4; nt++)
#pragma unroll
            for (int q = 0; q < 4; q++) oacc[mt][nt][q] = 0.0f;
    float mrun[2][2] = {{-1e30f, -1e30f}, {-1e30f, -1e30f}};
    float lrun[2][2] = {{0.0f, 0.0f}, {0.0f, 0.0f}};
    const float C2 = 0.17677669529663687f * 1.4426950408889634f;

    for (int kb = 0; kb < 4; kb++) {
        float sacc[2][8][4];
#pragma unroll
        for (int mt = 0; mt < 2; mt++)
#pragma unroll
            for (int nt = 0; nt < 8; nt++)
#pragma unroll
                for (int q = 0; q < 4; q++) sacc[mt][nt][q] = 0.0f;

#pragma unroll
        for (int kc = 0; kc < 2; kc++) {
            uint32_t kf[4][4];
#pragma unroll
            for (int grp = 0; grp < 4; grp++) {
                uint32_t ad = Ks + (uint32_t)(kb * 64 + grp * 16 + (lane & 15)) * 80
                              + (lane >> 4) * 16 + kc * 32;
                LDSM_X4(kf[grp], ad);
            }
#pragma unroll
            for (int mt = 0; mt < 2; mt++)
#pragma unroll
                for (int nt = 0; nt < 8; nt++)
                    MMA16816(sacc[mt][nt], qf[mt][kc],
                             kf[nt >> 1][nt & 1], kf[nt >> 1][(nt & 1) + 2]);
        }

#pragma unroll
        for (int mt = 0; mt < 2; mt++)
#pragma unroll
            for (int hf = 0; hf < 2; hf++) {
                float mx = -1e30f;
#pragma unroll
                for (int nt = 0; nt < 8; nt++)
                    mx = fmaxf(mx, fmaxf(sacc[mt][nt][hf * 2], sacc[mt][nt][hf * 2 + 1]));
                mx = fmaxf(mx, __shfl_xor_sync(0xffffffffu, mx, 1));
                mx = fmaxf(mx, __shfl_xor_sync(0xffffffffu, mx, 2));
                float mold = mrun[mt][hf];
                float mnew = fmaxf(mold, mx);
                float corr = exp2f(C2 * (mold - mnew));
                mrun[mt][hf] = mnew;
                float sum = 0.0f;
#pragma unroll
                for (int nt = 0; nt < 8; nt++) {
                    float p0 = exp2f(C2 * (sacc[mt][nt][hf * 2] - mnew));
                    float p1 = exp2f(C2 * (sacc[mt][nt][hf * 2 + 1] - mnew));
                    sacc[mt][nt][hf * 2] = p0;
                    sacc[mt][nt][hf * 2 + 1] = p1;
                    sum += p0 + p1;
                }
                sum += __shfl_xor_sync(0xffffffffu, sum, 1);
                sum += __shfl_xor_sync(0xffffffffu, sum, 2);
                lrun[mt][hf] = lrun[mt][hf] * corr + sum;
#pragma unroll
                for (int nt = 0; nt < 4; nt++) {
                    oacc[mt][nt][hf * 2] *= corr;
                    oacc[mt][nt][hf * 2 + 1] *= corr;
                }
            }

#pragma unroll
        for (int kc4 = 0; kc4 < 4; kc4++) {
            uint32_t vf[2][4];
#pragma unroll
            for (int dg = 0; dg < 2; dg++) {
                uint32_t ad = Vs + (uint32_t)(kb * 64 + kc4 * 16 + (lane & 15)) * 80
                              + dg * 32 + (lane >> 4) * 16;
                LDSM_X4T(vf[dg], ad);
            }
#pragma unroll
            for (int mt = 0; mt < 2; mt++) {
                uint32_t a[4];
                a[0] = bf2u(sacc[mt][2 * kc4][0], sacc[mt][2 * kc4][1]);
                a[1] = bf2u(sacc[mt][2 * kc4][2], sacc[mt][2 * kc4][3]);
                a[2] = bf2u(sacc[mt][2 * kc4 + 1][0], sacc[mt][2 * kc4 + 1][1]);
                a[3] = bf2u(sacc[mt][2 * kc4 + 1][2], sacc[mt][2 * kc4 + 1][3]);
#pragma unroll
                for (int nt = 0; nt < 4; nt++)
                    MMA16816(oacc[mt][nt], a,
                             vf[nt >> 1][(nt & 1) * 2], vf[nt >> 1][(nt & 1) * 2 + 1]);
            }
        }
    }

#pragma unroll
    for (int mt = 0; mt < 2; mt++) {
        float inv0 = 1.0f / lrun[mt][0];
        float inv1 = 1.0f / lrun[mt][1];
        int row0 = win * 256 + qb + mt * 16 + (lane >> 2);
        int col = h * 32 + (lane & 3) * 2;
#pragma unroll
        for (int nt = 0; nt < 4; nt++) {
            *(uint32_t*)(out + (size_t)row0 * 256 + col + nt * 8) =
                bf2u(oacc[mt][nt][0] * inv0, oacc[mt][nt][1] * inv0);
            *(uint32_t*)(out + (size_t)(row0 + 8) * 256 + col + nt * 8) =
                bf2u(oacc[mt][nt][2] * inv1, oacc[mt][nt][3] * inv1);
        }
    }
}

// ---------------------------------------------------------------------------
__device__ __forceinline__ void decode_f(int f, int& fw, int& base_t,
                                         int& gwin, int& tt) {
    int b = f >> 10, h = (f >> 7) & 7, w = (f >> 4) & 7;
    int r1 = (f >> 2) & 3, r2 = f & 3;
    fw = (b * 8 + h) * 8 + w;
    base_t = r1 * 64 + r2 * 4;
    int gr = h * 4 + r1, gc = w * 4 + r2;
    gwin = b * 4 + (gr >> 4) * 2 + (gc >> 4);
    tt = (gr & 15) * 16 + (gc & 15);
}

__global__ void smsa_scatter_g_kernel(const float* __restrict__ g,
                                      float* __restrict__ out1) {
    int f = blockIdx.x, c = threadIdx.x;
    int fw, base_t, gwin, tt;
    decode_f(f, fw, base_t, gwin, tt);
    out1[((size_t)gwin * 256 + tt) * 256 + c] = g[(size_t)f * 256 + c];
}

__global__ __launch_bounds__(256) void smsa_xattn_kernel(
    const __nv_bfloat16* __restrict__ Q, const __nv_bfloat16* __restrict__ KV,
    __nv_bfloat16* __restrict__ AO) {
    int f = blockIdx.x;
    int h = threadIdx.x >> 5;
    int d = threadIdx.x & 31;
    int fw, base_t, gwin, tt;
    decode_f(f, fw, base_t, gwin, tt);
    float qd = __bfloat162float(Q[(size_t)f * 256 + h * 32 + d]);
    const float sc = 0.17677669529663687f;
    float s[16];
#pragma unroll
    for (int j = 0; j < 16; j++) {
        int t = base_t + (j >> 2) * 16 + (j & 3);
        float kd = __bfloat162float(KV[((size_t)(fw * 256 + t)) * 512 + h * 32 + d]);
        float pr = qd * kd;
#pragma unroll
        for (int o = 16; o > 0; o >>= 1)
            pr += __shfl_xor_sync(0xffffffffu, pr, o);
        s[j] = pr * sc;
    }
    float m = s[0];
#pragma unroll
    for (int j = 1; j < 16; j++) m = fmaxf(m, s[j]);
    float l = 0.0f, p[16];
#pragma unroll
    for (int j = 0; j < 16; j++) {
        p[j] = __expf(s[j] - m);
        l += p[j];
    }
    float inv = 1.0f / l;
    float acc = 0.0f;
#pragma unroll
    for (int j = 0; j < 16; j++) {
        int t = base_t + (j >> 2) * 16 + (j & 3);
        acc = fmaf(p[j], __bfloat162float(
                        KV[((size_t)(fw * 256 + t)) * 512 + 256 + h * 32 + d]),
                   acc);
    }
    AO[(size_t)f * 256 + h * 32 + d] = __float2bfloat16(acc * inv);
}

// ---------------------------------------------------------------------------
// Host side
// ---------------------------------------------------------------------------
static void run_hgemm_seg(const __nv_bfloat16* A, int lda,
                          const __nv_bfloat16* Bt0, const __nv_bfloat16* Bt1,
                          void* C0, void* C1, int ldc0, int ldc1,
                          const float* bias0, const float* bias1,
                          const float* res0, const float* res1, int ldr,
                          int M, int N, int K, int act, int outbf,
                          int mb1, int nbmax1) {
    dim3 grid(N / 128, M / 128);
    smsa_hgemm_kernel<<<grid, 128, GEMM_SMEM>>>(
        A, lda, Bt0, Bt1, C0, C1, ldc0, ldc1, bias0, bias1,
        res0, res1, ldr, K, act, outbf, mb1, nbmax1);
}

static void run_hgemm(const __nv_bfloat16* A, int lda, const __nv_bfloat16* Bt,
                      void* Cm, int ldc, const float* bias,
                      const float* res, int ldr, int M, int N, int K,
                      int act, int outbf) {
    run_hgemm_seg(A, lda, Bt, Bt, Cm, Cm, ldc, ldc, bias, bias, res, res, ldr,
                  M, N, K, act, outbf, 1 << 30, 1 << 30);
}

static void run_ln2(const float* x, __nv_bfloat16* y,
                    const float* g0, const float* b0,
                    const float* g1, const float* b1, int ntok, int bnd) {
    smsa_ln_kernel<<<ntok / 8, 256>>>(x, y, g0, b0, g1, b1, bnd);
}

extern "C" void kernel_launch(void* const* d_in, const int* in_sizes, int n_in,
                              void* d_out, int out_size) {
    const float* scale0 = (const float*)d_in[0];
    const float* scale1 = (const float*)d_in[1];
    const float* pe_w1 = (const float*)d_in[2];
    const float* pe_b1 = (const float*)d_in[3];
    const float* pe_w2 = (const float*)d_in[4];
    const float* ln1_g = (const float*)d_in[5];
    const float* ln1_b = (const float*)d_in[6];
    const float* wqkv = (const float*)d_in[7];
    const float* bqkv = (const float*)d_in[8];
    const float* wo = (const float*)d_in[9];
    const float* bo = (const float*)d_in[10];
    const float* ln2_g = (const float*)d_in[11];
    const float* ln2_b = (const float*)d_in[12];
    const float* mw1 = (const float*)d_in[13];
    const float* mb1 = (const float*)d_in[14];
    const float* mw2 = (const float*)d_in[15];
    const float* mb2 = (const float*)d_in[16];
    float* out = (float*)d_out;
    float* out0 = out;
    float* out1 = out + (size_t)65536 * 256;

    float *X, *PE, *G;
    __nv_bfloat16 *Hb, *QKVb, *Tb, *WT;
    cudaGetSymbolAddress((void**)&X, g_X);
    cudaGetSymbolAddress((void**)&PE, g_PE);
    cudaGetSymbolAddress((void**)&G, g_G);
    cudaGetSymbolAddress((void**)&Hb, g_Hb);
    cudaGetSymbolAddress((void**)&QKVb, g_QKVb);
    cudaGetSymbolAddress((void**)&Tb, g_Tb);
    cudaGetSymbolAddress((void**)&WT, g_WT);
    float* X1 = X + (size_t)65536 * 256;

    cudaFuncSetAttribute(smsa_fattn_kernel,
                         cudaFuncAttributeMaxDynamicSharedMemorySize, ATTN_SMEM);
    cudaFuncSetAttribute(smsa_hgemm_kernel,
                         cudaFuncAttributeMaxDynamicSharedMemorySize, GEMM_SMEM);

    const __nv_bfloat16 *wqkvT0 = WT + 0, *woT0 = WT + 196608;
    const __nv_bfloat16 *w1T0 = WT + 262144, *w2T0 = WT + 524288;
    const __nv_bfloat16 *wqkvT1 = WT + 786432, *woT1 = WT + 983040;
    const __nv_bfloat16 *w1T1 = WT + 1048576, *w2T1 = WT + 1310720;
    const float *ln1g0 = ln1_g, *ln1b0 = ln1_b;
    const float *ln2g0 = ln2_g, *ln2b0 = ln2_b;
    const float *ln1g1 = ln1_g + 256, *ln1b1 = ln1_b + 256;
    const float *ln2g1 = ln2_g + 256, *ln2b1 = ln2_b + 256;

    // 0) weight transposes, one launch
    {
        TrJobs J;
        const float* Ws[8] = {wqkv, wqkv + 196608, wo, wo + 65536,
                              mw1, mw1 + 262144, mw2, mw2 + 262144};
        __nv_bfloat16* Wts[8] = {WT + 0, WT + 786432, WT + 196608, WT + 983040,
                                 WT + 262144, WT + 1048576, WT + 524288, WT + 1310720};
        int Ks[8] = {256, 256, 256, 256, 256, 256, 1024, 1024};
        int Ns[8] = {768, 768, 256, 256, 1024, 1024, 256, 256};
        int b0 = 0;
        for (int i = 0; i < 8; i++) {
            J.W[i] = Ws[i]; J.Wt[i] = Wts[i]; J.K[i] = Ks[i]; J.N[i] = Ns[i];
            J.blk0[i] = b0;
            b0 += (Ks[i] / 32) * (Ns[i] / 32);
        }
        smsa_transpose_all_kernel<<<b0, dim3(32, 8)>>>(J);
    }

    // 1) position embeddings; scale0 add+LN1 fused
    smsa_posemb_kernel<<<dim3(256, 2), 256>>>(pe_w1, pe_b1, pe_w2, PE);
    smsa_add_pe_ln_kernel<<<8192, 256>>>(scale0, PE, X, Hb, ln1g0, ln1b0);

    // 2) add_pe(scale1) + pool + LN1(scale1) fused -> X1, Hb rows 65536+
    smsa_pool_ln_kernel<<<4096, 256>>>(X, scale1, PE + 65536, X1,
                                       Hb + (size_t)65536 * 256, ln1g1, ln1b1);

    // 3) MERGED sattn chain over 69632 rows
    run_hgemm_seg(Hb, 256, wqkvT0, wqkvT1,
                  QKVb, QKVb + (size_t)65536 * 768, 768, 768,
                  bqkv, bqkv + 768, nullptr, nullptr, 0,
                  NTOKA, 768, 256, 0, 1, MB1T, 6);
    smsa_fattn_kernel<<<(NTOKA / 256) * 8, 256, ATTN_SMEM>>>(QKVb, Hb);
    run_hgemm_seg(Hb, 256, woT0, woT1,
                  X, X1, 256, 256,
                  bo, bo + 256, X, X1, 256,
                  NTOKA, 256, 256, 0, 0, MB1T, 2);
    run_ln2(X, Hb, ln2g0, ln2b0, ln2g1, ln2b1, NTOKA, NTOK0);
    run_hgemm_seg(Hb, 256, w1T0, w1T1,
                  Tb, Tb + (size_t)65536 * 1024, 1024, 1024,
                  mb1, mb1 + 1024, nullptr, nullptr, 0,
                  NTOKA, 1024, 256, 1, 1, MB1T, 8);
    run_hgemm_seg(Tb, 1024, w2T0, w2T1,
                  out0, X1, 256, 256,
                  mb2, mb2 + 256, X, X1, 256,
                  NTOKA, 256, 1024, 0, 0, MB1T, 2);

    // cross kn LN: out0 -> Hb rows 0..65535
    run_ln2(out0, Hb, ln1g1, ln1b1, ln1g1, ln1b1, NTOK0, NTOK0);
    // gather + LN(G) -> G fp32, Hb rows 65536+ (bf16 qn)
    smsa_gather_ln_kernel<<<512, 256>>>(X1, G, Hb + (size_t)65536 * 256,
                                        ln1g1, ln1b1);

    __nv_bfloat16* Sqb = Tb;
    __nv_bfloat16* AOb = Tb + (size_t)4096 * 256;
    __nv_bfloat16* Sgb = Tb + (size_t)2 * 4096 * 256;
    __nv_bfloat16* Thb = Tb + (size_t)3 * 4096 * 256;

    // 4) segmented: seg0 = cross K|V (65536 x 512), seg1 = Sq (4096 x 256)
    run_hgemm_seg(Hb, 256, wqkvT1 + 256 * 256, wqkvT1,
                  QKVb, Sqb, 512, 256,
                  bqkv + 768 + 256, bqkv + 768, nullptr, nullptr, 0,
                  NTOKA, 512, 256, 0, 1, MB1T, 2);

    smsa_xattn_kernel<<<4096, 256>>>(Sqb, QKVb, AOb);
    run_hgemm(AOb, 256, woT1, G, 256, bo + 256, G, 256, NTOK1, 256, 256, 0, 0);
    run_ln2(G, Sgb, ln2g1, ln2b1, ln2g1, ln2b1, NTOK1, NTOK1);
    run_hgemm(Sgb, 256, w1T1, Thb, 1024, mb1 + 1024, nullptr, 0,
              NTOK1, 1024, 256, 1, 1);
    run_hgemm(Thb, 1024, w2T1, G, 256, mb2 + 256, G, 256, NTOK1, 256, 1024, 0, 0);

    // 5) scatter g back to o1 window layout
    smsa_scatter_g_kernel<<<4096, 256>>>(G, out1);
}